// round 5
// baseline (speedup 1.0000x reference)
#include <cuda_runtime.h>
#include <math.h>

#define NN    8192
#define HN    4096
#define QN    2048
#define MODES 16
#define ROWS  4096          /* BATCH*CH */
#define KSPL  8             /* forward m-splits */
#define MSPL  256           /* m per split = QN/KSPL */

// Scratch (__device__ globals: allocation-free rule)
__device__ float g_FBf[QN*32];             // fwd basis, grouped, x0.5 at m=0
__device__ float g_FBi[QN*32];             // inv basis, grouped
__device__ float g_partial[KSPL*ROWS*32];  // fwd partial sums
__device__ float g_CS[ROWS*32];            // reduced fwd sums (+boundary)
__device__ float g_C2[ROWS*32];            // irfft coefs, grouped A/B
__device__ float g_WrT[MODES*4096];        // weights transposed: [k][i*64+o]
__device__ float g_WiT[MODES*4096];

// Grouped column layout c' = 0..31:
//   j = c'&7, odd = (c'>>3)&1, k = 2j+odd
//   c' 0..7  : cos, even k     c' 8..15 : cos, odd k
//   c' 16..23: sin, even k     c' 24..31: sin, odd k
__global__ void init_tables(const float* __restrict__ wr,
                            const float* __restrict__ wi) {
    int idx = blockIdx.x * blockDim.x + threadIdx.x;
    if (idx >= QN * 32) return;   // == 65536 == weight count too
    // --- basis ---
    {
        int m = idx >> 5, c = idx & 31;
        int j = c & 7;
        int kk = 2 * j + ((c >> 3) & 1);
        int t = (kk * m) & (NN - 1);
        double ang = (double)t * (6.283185307179586476925286766559 / (double)NN);
        float v = (float)((c < 16) ? cos(ang) : sin(ang));
        g_FBi[idx] = v;
        g_FBf[idx] = (m == 0) ? 0.5f * v : v;  // m=0 quartet double-counts x[0],x[4096]
    }
    // --- weight transpose: wr[(i*64+o)*16+k] -> g_WrT[k][i*64+o] ---
    {
        int io = idx >> 4, k = idx & 15;
        g_WrT[k * 4096 + io] = wr[idx];
        g_WiT[k * 4096 + io] = wi[idx];
    }
}

// ---------------------------------------------------------------------------
// Forward (folded): CS[row][c'] = sum_{m=0}^{2047} combo_{class(c')}[row][m] * FBf[m][c']
// combos from quartet {m, 4096-m, 4096+m, (8192-m)&8191}:
//   a = (v0+v3)+(v1+v2)   even-cos     cc = (v0+v3)-(v1+v2)  odd-cos
//   b = (v0-v3)+(v2-v1)   even-sin     d  = (v0-v3)-(v2-v1)  odd-sin
// Block: 64 rows, 128 thr, tile 4r x 4c, K-split 8 (256 m each, 8 chunks of 32).
// ---------------------------------------------------------------------------
__global__ __launch_bounds__(128) void fwd_dft(const float* __restrict__ x) {
    __shared__ float  cmb[4 * 2178];
    __shared__ float4 bs[32][8];

    const int tid  = threadIdx.x;
    const int row0 = blockIdx.x * 64;
    const int ms0  = blockIdx.y * MSPL;
    const int tr   = tid >> 3;            // 0..15 -> rows 4*tr..4*tr+3
    const int tc   = tid & 7;             // 0..7  -> cols 4*tc..4*tc+3
    const int cls  = tc >> 1;             // 0..3  class of this thread's columns

    float acc[4][4];
    #pragma unroll
    for (int j = 0; j < 4; j++)
        #pragma unroll
        for (int q = 0; q < 4; q++) acc[j][q] = 0.f;

    for (int ch = 0; ch < 8; ch++) {
        const int m0 = ms0 + ch * 32;

        #pragma unroll
        for (int i = 0; i < 4; i++) {
            int q   = tid + i * 128;
            int row = q >> 3;
            int g   = q & 7;
            const float* xr = x + (size_t)(row0 + row) * NN;
            int mb = m0 + 4 * g;
            float4 v0 = *(const float4*)(xr + mb);
            float4 v2 = *(const float4*)(xr + HN + mb);
            float v0a[4] = {v0.x, v0.y, v0.z, v0.w};
            float v2a[4] = {v2.x, v2.y, v2.z, v2.w};
            float* base = cmb + row * 34 + 4 * g;
            #pragma unroll
            for (int j = 0; j < 4; j++) {
                int mm = mb + j;
                float v1 = xr[HN - mm];
                float v3 = xr[(NN - mm) & (NN - 1)];
                float p = v0a[j] + v3, q2 = v0a[j] - v3;
                float r = v1 + v2a[j], s = v2a[j] - v1;
                base[0 * 2178 + j] = p + r;   // a   (even-cos)
                base[1 * 2178 + j] = p - r;   // cc  (odd-cos)
                base[2 * 2178 + j] = q2 + s;  // b   (even-sin)
                base[3 * 2178 + j] = q2 - s;  // d   (odd-sin)
            }
        }
        #pragma unroll
        for (int i = 0; i < 2; i++) {
            int q  = tid + i * 128;
            int k  = q >> 3;
            int cq = q & 7;
            bs[k][cq] = *(const float4*)(g_FBf + (size_t)(m0 + k) * 32 + 4 * cq);
        }
        __syncthreads();

        const float* cbase = cmb + cls * 2178;
        #pragma unroll
        for (int m = 0; m < 32; m++) {
            float4 bv = bs[m][tc];
            #pragma unroll
            for (int j = 0; j < 4; j++) {
                float xv = cbase[(4 * tr + j) * 34 + m];
                acc[j][0] += xv * bv.x;
                acc[j][1] += xv * bv.y;
                acc[j][2] += xv * bv.z;
                acc[j][3] += xv * bv.w;
            }
        }
        __syncthreads();
    }

    #pragma unroll
    for (int j = 0; j < 4; j++) {
        int rg = row0 + 4 * tr + j;
        float4 v = make_float4(acc[j][0], acc[j][1], acc[j][2], acc[j][3]);
        *(float4*)(g_partial + ((size_t)blockIdx.y * ROWS + rg) * 32 + 4 * tc) = v;
    }
}

// ---------------------------------------------------------------------------
// Reduce K-splits + m=2048 boundary term. Fully coalesced.
//   c<8   (cos, even k=2j): += (x[2048]+x[6144]) * (-1)^j
//   c>=24 (sin, odd  k)   : += (x[2048]-x[6144]) * (-1)^j
// ---------------------------------------------------------------------------
__global__ __launch_bounds__(256) void reduce_cs(const float* __restrict__ x) {
    int q = blockIdx.x * blockDim.x + threadIdx.x;
    if (q >= ROWS * 32) return;
    int row = q >> 5, c = q & 31;
    float s = 0.f;
    #pragma unroll
    for (int ks = 0; ks < KSPL; ks++)
        s += g_partial[(size_t)ks * ROWS * 32 + q];
    float xa = x[(size_t)row * NN + QN];
    float xb = x[(size_t)row * NN + 3 * QN];
    int j = c & 7;
    float sg = (j & 1) ? -1.f : 1.f;
    if (c < 8)       s += (xa + xb) * sg;
    else if (c >= 24) s += (xa - xb) * sg;
    g_CS[q] = s;
}

// ---------------------------------------------------------------------------
// Mix: apply complex weights over in_ch, emit grouped irfft coefs A/B.
// Grid (16 k, 4 bg), 256 threads. Weights staged once (coalesced, from
// transposed copy); each thread (bl0,o) computes 4 batches.
// ---------------------------------------------------------------------------
__global__ __launch_bounds__(256) void mix() {
    __shared__ float sWr[64 * 64];
    __shared__ float sWi[64 * 64];
    __shared__ float sXc[16 * 64];
    __shared__ float sXs[16 * 64];
    const int k   = blockIdx.x;
    const int bg  = blockIdx.y;
    const int tid = threadIdx.x;

    const int cA = (k & 1) ? 8 + (k >> 1) : (k >> 1);
    const int cS = cA + 16;

    const float* wrk = g_WrT + (size_t)k * 4096;
    const float* wik = g_WiT + (size_t)k * 4096;
    #pragma unroll
    for (int i = 0; i < 4; i++) {
        int q = tid + i * 256;                       // float4 index 0..1023
        ((float4*)sWr)[q] = ((const float4*)wrk)[q];
        ((float4*)sWi)[q] = ((const float4*)wik)[q];
    }
    #pragma unroll
    for (int i = 0; i < 4; i++) {
        int q   = tid + i * 256;                     // entry: (bloc = q>>6, i = q&63)
        int row = (bg * 16 + (q >> 6)) * 64 + (q & 63);
        sXc[q] = g_CS[(size_t)row * 32 + cA];
        sXs[q] = g_CS[(size_t)row * 32 + cS];
    }
    __syncthreads();

    const int o   = tid & 63;
    const int bl0 = tid >> 6;
    const float invN = 1.0f / (float)NN;

    #pragma unroll
    for (int bb = 0; bb < 4; bb++) {
        int bloc = bl0 * 4 + bb;
        float cre = 0.f, cim = 0.f;
        #pragma unroll 8
        for (int i = 0; i < 64; i++) {
            float a   = sXc[bloc * 64 + i];
            float s   = sXs[bloc * 64 + i];
            float wre = sWr[i * 64 + o];
            float wim = sWi[i * 64 + o];
            cre += a * wre + s * wim;
            cim += a * wim - s * wre;
        }
        float A  = (k == 0 ? cre : 2.f * cre) * invN;
        float Bc = (k == 0 ? 0.f : -2.f * cim * invN);
        int rowo = (bg * 16 + bloc) * 64 + o;
        g_C2[(size_t)rowo * 32 + cA] = A;
        g_C2[(size_t)rowo * 32 + cS] = Bc;
    }
}

// ---------------------------------------------------------------------------
// Inverse (folded): per lane (base n), basis in 32 regs; per row: broadcast-LDS
// coefs, 32 FFMA -> 4 partials -> 4 outputs {n, 8192-n, 4096-n, 4096+n}.
// n==0 lane also emits n=2048/6144 (theta = pi*k/2 pattern).
// ---------------------------------------------------------------------------
__global__ __launch_bounds__(256) void inv_dft(float* __restrict__ y) {
    __shared__ float sC[64 * 32];
    const int tid  = threadIdx.x;
    const int w    = tid >> 5;
    const int ln   = tid & 31;
    const int row0 = blockIdx.y * 64;
    const int n    = blockIdx.x * 256 + w * 32 + ln;   // 0..2047

    #pragma unroll
    for (int i = 0; i < 2; i++) {
        int q = tid + i * 256;
        *(float4*)(sC + 4 * q) = *(const float4*)(g_C2 + (size_t)row0 * 32 + 4 * q);
    }

    float bas[32];
    #pragma unroll
    for (int i = 0; i < 8; i++) {
        float4 v = *(const float4*)(g_FBi + (size_t)n * 32 + 4 * i);
        bas[4*i+0] = v.x; bas[4*i+1] = v.y; bas[4*i+2] = v.z; bas[4*i+3] = v.w;
    }
    __syncthreads();

    const int nrev = (NN - n) & (NN - 1);
    const int nm   = HN - n;
    const int np   = HN + n;

    for (int r = 0; r < 64; r++) {
        float cf[32];
        const float* cp = sC + r * 32;
        #pragma unroll
        for (int i = 0; i < 8; i++) {
            float4 v = *(const float4*)(cp + 4 * i);   // broadcast LDS.128
            cf[4*i+0] = v.x; cf[4*i+1] = v.y; cf[4*i+2] = v.z; cf[4*i+3] = v.w;
        }
        float Ee = 0.f, Eo = 0.f, Oe = 0.f, Oo = 0.f;
        #pragma unroll
        for (int j = 0; j < 8; j++) {
            Ee += cf[j]      * bas[j];
            Eo += cf[8 + j]  * bas[8 + j];
            Oe += cf[16 + j] * bas[16 + j];
            Oo += cf[24 + j] * bas[24 + j];
        }
        float P = Ee + Eo, Q = Ee - Eo, R = Oe + Oo, S = Oe - Oo;
        size_t rb = (size_t)(row0 + r) * NN;
        y[rb + n]    = P + R;
        y[rb + nrev] = P - R;
        y[rb + nm]   = Q - S;
        y[rb + np]   = Q + S;

        if (n == 0) {   // absorb old fix2048: outputs n=2048, 6144
            float da = 0.f, db = 0.f;
            #pragma unroll
            for (int j = 0; j < 8; j++) {
                float sg = (j & 1) ? -1.f : 1.f;
                da += sg * cf[j];        // A_{2j} * (-1)^j
                db += sg * cf[24 + j];   // B_{2j+1} * (-1)^j
            }
            y[rb + QN]     = da + db;
            y[rb + 3 * QN] = da - db;
        }
    }
}

// ---------------------------------------------------------------------------
extern "C" void kernel_launch(void* const* d_in, const int* in_sizes, int n_in,
                              void* d_out, int out_size) {
    const float* x  = (const float*)d_in[0];
    const float* wr = (const float*)d_in[1];
    const float* wi = (const float*)d_in[2];
    float*       y  = (float*)d_out;

    init_tables<<<(QN * 32 + 255) / 256, 256>>>(wr, wi);
    fwd_dft<<<dim3(ROWS / 64, KSPL), 128>>>(x);
    reduce_cs<<<(ROWS * 32 + 255) / 256, 256>>>(x);
    mix<<<dim3(MODES, 4), 256>>>();
    inv_dft<<<dim3(QN / 256, ROWS / 64), 256>>>(y);
}

// round 6
// speedup vs baseline: 1.7041x; 1.7041x over previous
#include <cuda_runtime.h>
#include <math.h>

#define NN    8192
#define HN    4096
#define QN    2048
#define MODES 16
#define ROWS  4096          /* BATCH*CH */
#define KSPL  8             /* forward m-splits */
#define MSPL  256           /* m per split = QN/KSPL */

/* fwd combo smem geometry: [cls][m][row], row-stride T, class-stride S       */
#define CMB_T 68            /* 64 rows + pad; T mod 32 = 4, T mod 4 = 0       */
#define CMB_S 2184          /* 32*68 + 8;    S mod 32 = 8, S mod 4 = 0        */

// Scratch (__device__ globals: allocation-free rule)
__device__ float g_FBf[QN*32];             // fwd basis, grouped, x0.5 at m=0
__device__ float g_FBi[QN*32];             // inv basis, grouped
__device__ float g_partial[KSPL*ROWS*32];  // fwd partial sums
__device__ float g_CS[ROWS*32];            // reduced fwd sums (+boundary)
__device__ float g_C2[ROWS*32];            // irfft coefs, grouped A/B
__device__ float g_WrT[MODES*4096];        // weights transposed: [k][i*64+o]
__device__ float g_WiT[MODES*4096];

// Grouped column layout c' = 0..31:
//   j = c'&7, odd = (c'>>3)&1, k = 2j+odd
//   c' 0..7  : cos, even k     c' 8..15 : cos, odd k
//   c' 16..23: sin, even k     c' 24..31: sin, odd k
__global__ void init_tables(const float* __restrict__ wr,
                            const float* __restrict__ wi) {
    int idx = blockIdx.x * blockDim.x + threadIdx.x;
    if (idx >= QN * 32) return;   // == 65536 == weight count too
    // --- basis: angle = 2*pi*t/8192 = pi * (t/4096), t exact dyadic ---
    {
        int m = idx >> 5, c = idx & 31;
        int j = c & 7;
        int kk = 2 * j + ((c >> 3) & 1);
        int t = (kk * m) & (NN - 1);
        float a = (float)t * (1.0f / (float)HN);
        float v = (c < 16) ? cospif(a) : sinpif(a);
        g_FBi[idx] = v;
        g_FBf[idx] = (m == 0) ? 0.5f * v : v;  // m=0 quartet double-counts x[0],x[4096]
    }
    // --- weight transpose: wr[(i*64+o)*16+k] -> g_WrT[k][i*64+o] ---
    {
        int io = idx >> 4, k = idx & 15;
        g_WrT[k * 4096 + io] = wr[idx];
        g_WiT[k * 4096 + io] = wi[idx];
    }
}

// ---------------------------------------------------------------------------
// Forward (folded): CS[row][c'] = sum_m combo_{cls}[row][m] * FBf[m][c']
// Quartet {m, 4096-m, 4096+m, (8192-m)&8191} -> 4 class combos.
// Block: 64 rows, 128 thr, tile 4r x 4c, K-split 8. Combos stored [cls][m][row]
// so the compute loop is 2x LDS.128 per 16 FFMA, provably conflict-free.
// ---------------------------------------------------------------------------
__global__ __launch_bounds__(128) void fwd_dft(const float* __restrict__ x) {
    __shared__ float  cmb[4 * CMB_S];
    __shared__ float4 bs[32][8];

    const int tid  = threadIdx.x;
    const int row0 = blockIdx.x * 64;
    const int ms0  = blockIdx.y * MSPL;
    const int tr   = tid >> 3;            // 0..15 -> rows 4*tr..4*tr+3
    const int tc   = tid & 7;             // 0..7  -> cols 4*tc..4*tc+3
    const int cls  = tc >> 1;             // 0..3

    float acc[4][4];
    #pragma unroll
    for (int j = 0; j < 4; j++)
        #pragma unroll
        for (int q = 0; q < 4; q++) acc[j][q] = 0.f;

    for (int ch = 0; ch < 8; ch++) {
        const int m0 = ms0 + ch * 32;

        // stage combos: thread (row, g) covers m = g + 8*jj (conflict-free STS)
        #pragma unroll
        for (int i = 0; i < 4; i++) {
            int q   = tid + i * 128;
            int row = q >> 3;
            int g   = q & 7;
            const float* xr = x + (size_t)(row0 + row) * NN;
            #pragma unroll
            for (int jj = 0; jj < 4; jj++) {
                int mi = g + 8 * jj;       // 0..31
                int mm = m0 + mi;
                float v0 = xr[mm];
                float v1 = xr[HN - mm];
                float v2 = xr[HN + mm];
                float v3 = xr[(NN - mm) & (NN - 1)];
                float p = v0 + v3, q2 = v0 - v3;
                float r = v1 + v2, s  = v2 - v1;
                float* base = cmb + mi * CMB_T + row;
                base[0 * CMB_S] = p + r;    // even-cos
                base[1 * CMB_S] = p - r;    // odd-cos
                base[2 * CMB_S] = q2 + s;   // even-sin
                base[3 * CMB_S] = q2 - s;   // odd-sin
            }
        }
        // stage basis tile (32 m x 32 c)
        #pragma unroll
        for (int i = 0; i < 2; i++) {
            int q  = tid + i * 128;
            int k  = q >> 3;
            int cq = q & 7;
            bs[k][cq] = *(const float4*)(g_FBf + (size_t)(m0 + k) * 32 + 4 * cq);
        }
        __syncthreads();

        const float* cbase = cmb + cls * CMB_S + 4 * tr;
        #pragma unroll
        for (int m = 0; m < 32; m++) {
            float4 xv = *(const float4*)(cbase + m * CMB_T);  // rows 4tr..4tr+3
            float4 bv = bs[m][tc];
            acc[0][0] += xv.x * bv.x; acc[0][1] += xv.x * bv.y;
            acc[0][2] += xv.x * bv.z; acc[0][3] += xv.x * bv.w;
            acc[1][0] += xv.y * bv.x; acc[1][1] += xv.y * bv.y;
            acc[1][2] += xv.y * bv.z; acc[1][3] += xv.y * bv.w;
            acc[2][0] += xv.z * bv.x; acc[2][1] += xv.z * bv.y;
            acc[2][2] += xv.z * bv.z; acc[2][3] += xv.z * bv.w;
            acc[3][0] += xv.w * bv.x; acc[3][1] += xv.w * bv.y;
            acc[3][2] += xv.w * bv.z; acc[3][3] += xv.w * bv.w;
        }
        __syncthreads();
    }

    #pragma unroll
    for (int j = 0; j < 4; j++) {
        int rg = row0 + 4 * tr + j;
        float4 v = make_float4(acc[j][0], acc[j][1], acc[j][2], acc[j][3]);
        *(float4*)(g_partial + ((size_t)blockIdx.y * ROWS + rg) * 32 + 4 * tc) = v;
    }
}

// ---------------------------------------------------------------------------
// Reduce K-splits + m=2048 boundary term. Fully coalesced.
// ---------------------------------------------------------------------------
__global__ __launch_bounds__(256) void reduce_cs(const float* __restrict__ x) {
    int q = blockIdx.x * blockDim.x + threadIdx.x;
    if (q >= ROWS * 32) return;
    int row = q >> 5, c = q & 31;
    float s = 0.f;
    #pragma unroll
    for (int ks = 0; ks < KSPL; ks++)
        s += g_partial[(size_t)ks * ROWS * 32 + q];
    float xa = x[(size_t)row * NN + QN];
    float xb = x[(size_t)row * NN + 3 * QN];
    int j = c & 7;
    float sg = (j & 1) ? -1.f : 1.f;
    if (c < 8)        s += (xa + xb) * sg;
    else if (c >= 24) s += (xa - xb) * sg;
    g_CS[q] = s;
}

// ---------------------------------------------------------------------------
// Mix: grid (16 k, 16 bg), 256 thr. Each block: 4 batches; thread (b_local, o).
// Weights staged coalesced from transposed copy; 256 blocks keep chip busy.
// ---------------------------------------------------------------------------
__global__ __launch_bounds__(256) void mix() {
    __shared__ float sWr[64 * 64];
    __shared__ float sWi[64 * 64];
    __shared__ float sXc[4 * 64];
    __shared__ float sXs[4 * 64];
    const int k   = blockIdx.x;
    const int bg  = blockIdx.y;
    const int tid = threadIdx.x;

    const int cA = (k & 1) ? 8 + (k >> 1) : (k >> 1);
    const int cS = cA + 16;

    const float* wrk = g_WrT + (size_t)k * 4096;
    const float* wik = g_WiT + (size_t)k * 4096;
    #pragma unroll
    for (int i = 0; i < 4; i++) {
        int q = tid + i * 256;
        ((float4*)sWr)[q] = ((const float4*)wrk)[q];
        ((float4*)sWi)[q] = ((const float4*)wik)[q];
    }
    {   // 256 entries: (b_local = tid>>6, i = tid&63)
        int row = (bg * 4 + (tid >> 6)) * 64 + (tid & 63);
        sXc[tid] = g_CS[(size_t)row * 32 + cA];
        sXs[tid] = g_CS[(size_t)row * 32 + cS];
    }
    __syncthreads();

    const int o  = tid & 63;
    const int bl = tid >> 6;
    float cre = 0.f, cim = 0.f;
    #pragma unroll 8
    for (int i = 0; i < 64; i++) {
        float a   = sXc[bl * 64 + i];
        float s   = sXs[bl * 64 + i];
        float wre = sWr[i * 64 + o];
        float wim = sWi[i * 64 + o];
        cre += a * wre + s * wim;
        cim += a * wim - s * wre;
    }
    const float invN = 1.0f / (float)NN;
    float A  = (k == 0 ? cre : 2.f * cre) * invN;
    float Bc = (k == 0 ? 0.f : -2.f * cim * invN);
    int rowo = (bg * 4 + bl) * 64 + o;
    g_C2[(size_t)rowo * 32 + cA] = A;
    g_C2[(size_t)rowo * 32 + cS] = Bc;
}

// ---------------------------------------------------------------------------
// Inverse (folded): 2 base-n per thread (basis in 64 regs). Per row: one set
// of broadcast LDS.128 coef loads feeds 64 FFMA -> 8 outputs.
// n==0 lane also emits n=2048/6144.
// ---------------------------------------------------------------------------
__global__ __launch_bounds__(256) void inv_dft(float* __restrict__ y) {
    __shared__ float sC[64 * 32];
    const int tid  = threadIdx.x;
    const int w    = tid >> 5;
    const int ln   = tid & 31;
    const int row0 = blockIdx.y * 64;
    const int n1   = blockIdx.x * 512 + w * 32 + ln;   // [bx*512, bx*512+256)
    const int n2   = n1 + 256;

    #pragma unroll
    for (int i = 0; i < 2; i++) {
        int q = tid + i * 256;
        *(float4*)(sC + 4 * q) = *(const float4*)(g_C2 + (size_t)row0 * 32 + 4 * q);
    }

    float b1[32], b2[32];
    #pragma unroll
    for (int i = 0; i < 8; i++) {
        float4 v = *(const float4*)(g_FBi + (size_t)n1 * 32 + 4 * i);
        b1[4*i+0] = v.x; b1[4*i+1] = v.y; b1[4*i+2] = v.z; b1[4*i+3] = v.w;
        float4 u = *(const float4*)(g_FBi + (size_t)n2 * 32 + 4 * i);
        b2[4*i+0] = u.x; b2[4*i+1] = u.y; b2[4*i+2] = u.z; b2[4*i+3] = u.w;
    }
    __syncthreads();

    const int nrev1 = (NN - n1) & (NN - 1), nm1 = HN - n1, np1 = HN + n1;
    const int nrev2 = NN - n2,              nm2 = HN - n2, np2 = HN + n2;

    for (int r = 0; r < 64; r++) {
        float cf[32];
        const float* cp = sC + r * 32;
        #pragma unroll
        for (int i = 0; i < 8; i++) {
            float4 v = *(const float4*)(cp + 4 * i);   // broadcast LDS.128
            cf[4*i+0] = v.x; cf[4*i+1] = v.y; cf[4*i+2] = v.z; cf[4*i+3] = v.w;
        }
        size_t rb = (size_t)(row0 + r) * NN;

        float Ee = 0.f, Eo = 0.f, Oe = 0.f, Oo = 0.f;
        #pragma unroll
        for (int j = 0; j < 8; j++) {
            Ee += cf[j]      * b1[j];
            Eo += cf[8 + j]  * b1[8 + j];
            Oe += cf[16 + j] * b1[16 + j];
            Oo += cf[24 + j] * b1[24 + j];
        }
        {
            float P = Ee + Eo, Q = Ee - Eo, R = Oe + Oo, S = Oe - Oo;
            y[rb + n1]    = P + R;
            y[rb + nrev1] = P - R;
            y[rb + nm1]   = Q - S;
            y[rb + np1]   = Q + S;
        }
        Ee = 0.f; Eo = 0.f; Oe = 0.f; Oo = 0.f;
        #pragma unroll
        for (int j = 0; j < 8; j++) {
            Ee += cf[j]      * b2[j];
            Eo += cf[8 + j]  * b2[8 + j];
            Oe += cf[16 + j] * b2[16 + j];
            Oo += cf[24 + j] * b2[24 + j];
        }
        {
            float P = Ee + Eo, Q = Ee - Eo, R = Oe + Oo, S = Oe - Oo;
            y[rb + n2]    = P + R;
            y[rb + nrev2] = P - R;
            y[rb + nm2]   = Q - S;
            y[rb + np2]   = Q + S;
        }

        if (n1 == 0) {   // outputs n=2048, 6144
            float da = 0.f, db = 0.f;
            #pragma unroll
            for (int j = 0; j < 8; j++) {
                float sg = (j & 1) ? -1.f : 1.f;
                da += sg * cf[j];        // A_{2j} * (-1)^j
                db += sg * cf[24 + j];   // B_{2j+1} * (-1)^j
            }
            y[rb + QN]     = da + db;
            y[rb + 3 * QN] = da - db;
        }
    }
}

// ---------------------------------------------------------------------------
extern "C" void kernel_launch(void* const* d_in, const int* in_sizes, int n_in,
                              void* d_out, int out_size) {
    const float* x  = (const float*)d_in[0];
    const float* wr = (const float*)d_in[1];
    const float* wi = (const float*)d_in[2];
    float*       y  = (float*)d_out;

    init_tables<<<(QN * 32 + 255) / 256, 256>>>(wr, wi);
    fwd_dft<<<dim3(ROWS / 64, KSPL), 128>>>(x);
    reduce_cs<<<(ROWS * 32 + 255) / 256, 256>>>(x);
    mix<<<dim3(MODES, 16), 256>>>();
    inv_dft<<<dim3(QN / 512, ROWS / 64), 256>>>(y);
}